// round 7
// baseline (speedup 1.0000x reference)
#include <cuda_runtime.h>
#include <cuda_bf16.h>
#include <math.h>
#include <stdint.h>

// Model dims
#define LNUM 12
#define DMODEL 768
#define NHEAD 6
#define HDIM 128
#define FFDIM 3072
#define VOCAB 65536
#define SEQ 2048
#define EPSV 1e-5f
#define CAPV 30.0f

#define K3D (3 * DMODEL)    // 2304
#define K3F (3 * FFDIM)     // 9216

// GEMM tiling: CTA tile 128(M) x 64(N), BK=64, 8 warps of 32x32, 2-stage
#define BM 128
#define BN 64
#define LDS 72
#define STAGE_A (BM * LDS)             // elems
#define STAGE_B (BN * LDS)
#define STAGE_ELEMS (STAGE_A + STAGE_B)
#define SMEM_BYTES (2 * STAGE_ELEMS * 2)   // ~55.3 KB

// ---------------- scratch (static device arrays; no allocation) -------------
__device__ float g_x[SEQ * DMODEL];
__device__ float g_big[SEQ * K3D];
__device__ float g_q[SEQ * DMODEL];
__device__ float g_k[SEQ * DMODEL];
__device__ float g_v[SEQ * DMODEL];
__device__ float g_rowsum[SEQ];
__device__ float g_tl[SEQ];

// K-interleaved bf16x3 weight planes: row n, cols [0,K)=hi,[K,2K)=lo,[2K,3K)=hi
__device__ __align__(16) __nv_bfloat16 w3_qkv[12LL * 2304 * K3D];
__device__ __align__(16) __nv_bfloat16 w3_proj[12LL * 768 * K3D];
__device__ __align__(16) __nv_bfloat16 w3_fc1[12LL * 3072 * K3D];
__device__ __align__(16) __nv_bfloat16 w3_fc2[12LL * 768 * K3F];
__device__ __align__(16) __nv_bfloat16 w3_lm[65536LL * K3D];

// K-interleaved activation planes: row t, cols [0,K)=hi,[K,2K)=hi,[2K,3K)=lo
__device__ __align__(16) __nv_bfloat16 an3[SEQ * K3D];
__device__ __align__(16) __nv_bfloat16 ah3[SEQ * K3F];

// ---------------- helpers ----------------------------------------------------
__device__ __forceinline__ void split2(float v, __nv_bfloat16& h, __nv_bfloat16& l) {
    h = __float2bfloat16(v);
    l = __float2bfloat16(v - __bfloat162float(h));
}

__device__ __forceinline__ float blockReduceSum(float v) {
    __shared__ float sh[32];
    __syncthreads();
    int lane = threadIdx.x & 31, wid = threadIdx.x >> 5;
    #pragma unroll
    for (int o = 16; o; o >>= 1) v += __shfl_xor_sync(0xffffffffu, v, o);
    if (lane == 0) sh[wid] = v;
    __syncthreads();
    int nw = blockDim.x >> 5;
    v = (threadIdx.x < nw) ? sh[threadIdx.x] : 0.f;
    if (wid == 0) {
        #pragma unroll
        for (int o = 16; o; o >>= 1) v += __shfl_xor_sync(0xffffffffu, v, o);
        if (lane == 0) sh[0] = v;
    }
    __syncthreads();
    return sh[0];
}

__device__ __forceinline__ void ldsm4(uint32_t (&r)[4], uint32_t addr) {
    asm volatile("ldmatrix.sync.aligned.m8n8.x4.shared.b16 {%0,%1,%2,%3},[%4];"
                 : "=r"(r[0]), "=r"(r[1]), "=r"(r[2]), "=r"(r[3]) : "r"(addr));
}

__device__ __forceinline__ void mma_bf16(float (&d)[4], const uint32_t (&a)[4],
                                         uint32_t b0, uint32_t b1) {
    asm volatile(
        "mma.sync.aligned.m16n8k16.row.col.f32.bf16.bf16.f32 "
        "{%0,%1,%2,%3},{%4,%5,%6,%7},{%8,%9},{%0,%1,%2,%3};"
        : "+f"(d[0]), "+f"(d[1]), "+f"(d[2]), "+f"(d[3])
        : "r"(a[0]), "r"(a[1]), "r"(a[2]), "r"(a[3]), "r"(b0), "r"(b1));
}

__device__ __forceinline__ void cp16(uint32_t dst, const void* src) {
    asm volatile("cp.async.cg.shared.global [%0], [%1], 16;" :: "r"(dst), "l"(src));
}
#define CP_COMMIT() asm volatile("cp.async.commit_group;")
#define CP_WAIT1()  asm volatile("cp.async.wait_group 1;")

// Load one stage: A[128,64] + B[64,64] bf16 -> padded smem.
// FULL coverage: A = 1024 chunks (4/thread), B = 512 chunks (2/thread).
__device__ __forceinline__ void load_stage(uint32_t sA, uint32_t sB,
                                           const __nv_bfloat16* gA,
                                           const __nv_bfloat16* gB,
                                           int Kp, int tid) {
    int ar = tid >> 1;              // 0..127
    int ac = (tid & 1) * 32;        // element col base: 0 or 32
    #pragma unroll
    for (int c = 0; c < 4; c++)
        cp16(sA + (uint32_t)(ar * LDS + ac + c * 8) * 2,
             gA + (size_t)ar * Kp + ac + c * 8);
    int br = tid >> 2;              // 0..63
    int bc = (tid & 3) * 16;        // 0,16,32,48
    #pragma unroll
    for (int c = 0; c < 2; c++)
        cp16(sB + (uint32_t)(br * LDS + bc + c * 8) * 2,
             gB + (size_t)br * Kp + bc + c * 8);
}

// ---------------- fused weight split: 5 tensors, ONE launch -------------------
// f32[N,K] -> bf16[N,3K] as [hi|lo|hi]
__device__ __forceinline__ void split_seg(const float4* s, __nv_bfloat16* d,
                                          long long n4, int K,
                                          long long gid, long long gstride) {
    for (long long i = gid; i < n4; i += gstride) {
        float4 v = s[i];
        long long o = i * 4;
        long long n = o / K;
        int k = (int)(o - n * K);
        __nv_bfloat16* r = d + n * 3LL * K + k;
        float vv[4] = {v.x, v.y, v.z, v.w};
        #pragma unroll
        for (int j = 0; j < 4; j++) {
            __nv_bfloat16 h, l;
            split2(vv[j], h, l);
            r[j] = h; r[K + j] = l; r[2 * K + j] = h;
        }
    }
}

__global__ void split_all_kernel(const float4* qkv, const float4* proj,
                                 const float4* fc1, const float4* fc2,
                                 const float4* lm,
                                 __nv_bfloat16* dqkv, __nv_bfloat16* dproj,
                                 __nv_bfloat16* dfc1, __nv_bfloat16* dfc2,
                                 __nv_bfloat16* dlm) {
    long long gid = blockIdx.x * (long long)blockDim.x + threadIdx.x;
    long long gs = gridDim.x * (long long)blockDim.x;
    split_seg(qkv, dqkv, 12LL * 2304 * 768 / 4, DMODEL, gid, gs);
    split_seg(proj, dproj, 12LL * 768 * 768 / 4, DMODEL, gid, gs);
    split_seg(fc1, dfc1, 12LL * 3072 * 768 / 4, DMODEL, gid, gs);
    split_seg(fc2, dfc2, 12LL * 768 * 3072 / 4, FFDIM, gid, gs);
    split_seg(lm, dlm, 65536LL * 768 / 4, DMODEL, gid, gs);
}

// ---------------- elementwise kernels ----------------------------------------
__global__ void embed_kernel(const int* __restrict__ idx,
                             const float* __restrict__ emb) {
    int t = blockIdx.x;
    int row = idx[t];
    const float* src = emb + (size_t)row * DMODEL;
    for (int i = threadIdx.x; i < DMODEL; i += blockDim.x)
        g_x[t * DMODEL + i] = src[i];
}

__global__ void rmsnorm_kernel(const float* __restrict__ x,
                               const float* __restrict__ w) {
    int t = blockIdx.x;
    const float* xr = x + (size_t)t * DMODEL;
    float s = 0.f;
    for (int i = threadIdx.x; i < DMODEL; i += blockDim.x) {
        float v = xr[i];
        s += v * v;
    }
    s = blockReduceSum(s);
    float r = rsqrtf(s / (float)DMODEL + EPSV);
    for (int i = threadIdx.x; i < DMODEL; i += blockDim.x) {
        float v = xr[i] * r * w[i];
        __nv_bfloat16 h, l;
        split2(v, h, l);
        size_t o = (size_t)t * K3D + i;
        an3[o] = h; an3[o + DMODEL] = h; an3[o + 2 * DMODEL] = l;
    }
}

__global__ void rope_kernel(const float* __restrict__ qkv,
                            const float* __restrict__ qw,
                            const float* __restrict__ kw) {
    int t = blockIdx.x, h = blockIdx.y, d = threadIdx.x;
    const float* base = qkv + (size_t)t * K3D;
    float qd = base[h * HDIM + d];
    float kd = base[DMODEL + h * HDIM + d];
    float vd = base[2 * DMODEL + h * HDIM + d];
    float qs = blockReduceSum(qd * qd);
    float ks = blockReduceSum(kd * kd);
    float qn = qd * rsqrtf(qs / (float)HDIM + EPSV) * qw[d];
    float kn = kd * rsqrtf(ks / (float)HDIM + EPSV) * kw[d];
    __shared__ float sq[HDIM], sk[HDIM];
    sq[d] = qn; sk[d] = kn;
    __syncthreads();
    float expo = -(float)((d & 63) * 2) / (float)HDIM;
    float invf = expf(expo * logf(10000.f));
    float ang = (float)t * invf;
    float c = cosf(ang), s = sinf(ang);
    float qr = (d < 64) ? -sq[d + 64] : sq[d - 64];
    float kr = (d < 64) ? -sk[d + 64] : sk[d - 64];
    size_t oidx = (size_t)t * DMODEL + h * HDIM + d;
    g_q[oidx] = qn * c + qr * s;
    g_k[oidx] = kn * c + kr * s;
    g_v[oidx] = vd;
}

// ---------------- attention: warp-per-query, online softmax ------------------
__global__ void attn_kernel() {
    const int h = blockIdx.y;
    const int qbase = blockIdx.x * 8;
    const int warp = threadIdx.x >> 5, lane = threadIdx.x & 31;
    const int qi = qbase + warp;
    __shared__ float Ks[32][HDIM];
    __shared__ float Vs[32][HDIM];
    float ql[4];
    #pragma unroll
    for (int j = 0; j < 4; j++)
        ql[j] = g_q[(size_t)qi * DMODEL + h * HDIM + lane + 32 * j];
    float m = -1e30f, l = 0.f;
    float acc[4] = {0.f, 0.f, 0.f, 0.f};
    int ntiles = (qbase + 8 + 31) >> 5;
    for (int tb = 0; tb < ntiles; tb++) {
        int kb = tb << 5;
        __syncthreads();
        for (int i = threadIdx.x; i < 32 * 32; i += 256) {
            int row = i >> 5, c4 = i & 31;
            ((float4*)Ks[row])[c4] =
                ((const float4*)(g_k + (size_t)(kb + row) * DMODEL + h * HDIM))[c4];
            ((float4*)Vs[row])[c4] =
                ((const float4*)(g_v + (size_t)(kb + row) * DMODEL + h * HDIM))[c4];
        }
        __syncthreads();
        int jmax = qi - kb + 1; if (jmax > 32) jmax = 32;
        for (int j = 0; j < jmax; j++) {
            float s = ql[0] * Ks[j][lane] + ql[1] * Ks[j][lane + 32] +
                      ql[2] * Ks[j][lane + 64] + ql[3] * Ks[j][lane + 96];
            #pragma unroll
            for (int o = 16; o; o >>= 1) s += __shfl_xor_sync(0xffffffffu, s, o);
            s *= 0.08838834764831845f;
            float mn = fmaxf(m, s);
            float corr = __expf(m - mn);
            float p = __expf(s - mn);
            l = l * corr + p;
            #pragma unroll
            for (int jj = 0; jj < 4; jj++)
                acc[jj] = acc[jj] * corr + p * Vs[j][lane + 32 * jj];
            m = mn;
        }
    }
    float inv = 1.f / l;
    #pragma unroll
    for (int jj = 0; jj < 4; jj++) {
        int i = h * HDIM + lane + 32 * jj;
        __nv_bfloat16 hh, ll;
        split2(acc[jj] * inv, hh, ll);
        size_t o = (size_t)qi * K3D + i;
        an3[o] = hh; an3[o + DMODEL] = hh; an3[o + 2 * DMODEL] = ll;
    }
}

// ---------------- bf16 GEMM: C[M,N] = A[M,Kp] * B[N,Kp]^T ---------------------
// CTA 128x64, BK=64, 8 warps (4 M x 2 N) of 32x32, 2-stage cp.async, 2 CTAs/SM.
// epi: 0 = f32 store, 1 = +res f32 store, 2 = relu^2 -> triple bf16 O3
__global__ void __launch_bounds__(256, 2)
gemm_kernel(const __nv_bfloat16* __restrict__ A, const __nv_bfloat16* __restrict__ B,
            float* __restrict__ C, const float* __restrict__ res,
            __nv_bfloat16* __restrict__ O3, int N, int Kp, int epi) {
    extern __shared__ __nv_bfloat16 smem[];
    const int tid = threadIdx.x, lane = tid & 31, wid = tid >> 5;
    const int wm = wid >> 1, wn = wid & 1;           // 4 x 2 warp grid
    const int m0 = blockIdx.x * BM, n0 = blockIdx.y * BN;
    const uint32_t sbase = (uint32_t)__cvta_generic_to_shared(smem);
    const uint32_t aS[2] = {sbase, sbase + STAGE_ELEMS * 2};
    const uint32_t bS[2] = {sbase + STAGE_A * 2, sbase + (STAGE_ELEMS + STAGE_A) * 2};
    const __nv_bfloat16* gA = A + (size_t)m0 * Kp;
    const __nv_bfloat16* gB = B + (size_t)n0 * Kp;

    float acc[2][4][4];
    #pragma unroll
    for (int a = 0; a < 2; a++)
        #pragma unroll
        for (int b = 0; b < 4; b++)
            #pragma unroll
            for (int c = 0; c < 4; c++) acc[a][b][c] = 0.f;

    const int nk = Kp / 64;
    load_stage(aS[0], bS[0], gA, gB, Kp, tid);
    CP_COMMIT();

    for (int k = 0; k < nk; k++) {
        if (k + 1 < nk)
            load_stage(aS[(k + 1) & 1], bS[(k + 1) & 1],
                       gA + (size_t)(k + 1) * 64, gB + (size_t)(k + 1) * 64,
                       Kp, tid);
        CP_COMMIT();
        CP_WAIT1();
        __syncthreads();
        uint32_t aB = aS[k & 1], bB = bS[k & 1];
        #pragma unroll
        for (int kh = 0; kh < 4; kh++) {
            uint32_t a[2][4], b[2][4];
            const int acol = kh * 16 + ((lane >> 4) << 3);
            #pragma unroll
            for (int mt = 0; mt < 2; mt++) {
                int arow = wm * 32 + mt * 16 + (lane & 15);
                ldsm4(a[mt], aB + (uint32_t)(arow * LDS + acol) * 2);
            }
            const int brow = wn * 32 + ((lane >> 4) << 3) + (lane & 7);
            const int bcol = kh * 16 + (((lane >> 3) & 1) << 3);
            #pragma unroll
            for (int p = 0; p < 2; p++)
                ldsm4(b[p], bB + (uint32_t)((brow + p * 16) * LDS + bcol) * 2);
            #pragma unroll
            for (int mt = 0; mt < 2; mt++)
                #pragma unroll
                for (int nt = 0; nt < 4; nt++)
                    mma_bf16(acc[mt][nt], a[mt], b[nt >> 1][(nt & 1) * 2],
                             b[nt >> 1][(nt & 1) * 2 + 1]);
        }
        __syncthreads();   // all warps done reading stage k before overwrite
    }
    #pragma unroll
    for (int mt = 0; mt < 2; mt++)
        #pragma unroll
        for (int nt = 0; nt < 4; nt++)
            #pragma unroll
            for (int r = 0; r < 4; r++) {
                int row = m0 + wm * 32 + mt * 16 + (lane >> 2) + (r >> 1) * 8;
                int col = n0 + wn * 32 + nt * 8 + (lane & 3) * 2 + (r & 1);
                float vv = acc[mt][nt][r];
                if (epi == 0) {
                    C[(size_t)row * N + col] = vv;
                } else if (epi == 1) {
                    size_t o = (size_t)row * N + col;
                    C[o] = vv + res[o];
                } else {
                    vv = fmaxf(vv, 0.f); vv = vv * vv;
                    __nv_bfloat16 h, l;
                    split2(vv, h, l);
                    size_t o = (size_t)row * 3 * N + col;
                    O3[o] = h; O3[o + N] = h; O3[o + 2 * N] = l;
                }
            }
}

// ---------------- lm_head: same GEMM + softcap/store/lse epilogue ------------
__global__ void __launch_bounds__(256, 2)
lmhead_kernel(const __nv_bfloat16* __restrict__ A, const __nv_bfloat16* __restrict__ B,
              float* __restrict__ out, const int* __restrict__ targets, int store) {
    const int N = VOCAB, Kp = K3D;
    extern __shared__ __nv_bfloat16 smem[];
    const int tid = threadIdx.x, lane = tid & 31, wid = tid >> 5;
    const int wm = wid >> 1, wn = wid & 1;
    const int m0 = blockIdx.x * BM, n0 = blockIdx.y * BN;
    const uint32_t sbase = (uint32_t)__cvta_generic_to_shared(smem);
    const uint32_t aS[2] = {sbase, sbase + STAGE_ELEMS * 2};
    const uint32_t bS[2] = {sbase + STAGE_A * 2, sbase + (STAGE_ELEMS + STAGE_A) * 2};
    const __nv_bfloat16* gA = A + (size_t)m0 * Kp;
    const __nv_bfloat16* gB = B + (size_t)n0 * Kp;

    float acc[2][4][4];
    #pragma unroll
    for (int a = 0; a < 2; a++)
        #pragma unroll
        for (int b = 0; b < 4; b++)
            #pragma unroll
            for (int c = 0; c < 4; c++) acc[a][b][c] = 0.f;

    const int nk = Kp / 64;
    load_stage(aS[0], bS[0], gA, gB, Kp, tid);
    CP_COMMIT();

    for (int k = 0; k < nk; k++) {
        if (k + 1 < nk)
            load_stage(aS[(k + 1) & 1], bS[(k + 1) & 1],
                       gA + (size_t)(k + 1) * 64, gB + (size_t)(k + 1) * 64,
                       Kp, tid);
        CP_COMMIT();
        CP_WAIT1();
        __syncthreads();
        uint32_t aB = aS[k & 1], bB = bS[k & 1];
        #pragma unroll
        for (int kh = 0; kh < 4; kh++) {
            uint32_t a[2][4], b[2][4];
            const int acol = kh * 16 + ((lane >> 4) << 3);
            #pragma unroll
            for (int mt = 0; mt < 2; mt++) {
                int arow = wm * 32 + mt * 16 + (lane & 15);
                ldsm4(a[mt], aB + (uint32_t)(arow * LDS + acol) * 2);
            }
            const int brow = wn * 32 + ((lane >> 4) << 3) + (lane & 7);
            const int bcol = kh * 16 + (((lane >> 3) & 1) << 3);
            #pragma unroll
            for (int p = 0; p < 2; p++)
                ldsm4(b[p], bB + (uint32_t)((brow + p * 16) * LDS + bcol) * 2);
            #pragma unroll
            for (int mt = 0; mt < 2; mt++)
                #pragma unroll
                for (int nt = 0; nt < 4; nt++)
                    mma_bf16(acc[mt][nt], a[mt], b[nt >> 1][(nt & 1) * 2],
                             b[nt >> 1][(nt & 1) * 2 + 1]);
        }
        __syncthreads();
    }
    // epilogue: softcap, bf16-rounded f32 store, per-row sumexp, target logit
    float ps[4] = {0.f, 0.f, 0.f, 0.f};
    #pragma unroll
    for (int mt = 0; mt < 2; mt++)
        #pragma unroll
        for (int nt = 0; nt < 4; nt++)
            #pragma unroll
            for (int r = 0; r < 4; r++) {
                int row = m0 + wm * 32 + mt * 16 + (lane >> 2) + (r >> 1) * 8;
                int col = n0 + wn * 32 + nt * 8 + (lane & 3) * 2 + (r & 1);
                float vv = CAPV * tanhf(acc[mt][nt][r] * (1.f / CAPV));
                if (store)
                    out[(size_t)row * N + col] =
                        __bfloat162float(__float2bfloat16(vv));
                ps[mt * 2 + (r >> 1)] += __expf(vv - CAPV);
                if (col == targets[row]) g_tl[row] = vv;
            }
    #pragma unroll
    for (int i = 0; i < 4; i++) {
        ps[i] += __shfl_xor_sync(0xffffffffu, ps[i], 1);
        ps[i] += __shfl_xor_sync(0xffffffffu, ps[i], 2);
    }
    if ((lane & 3) == 0) {
        #pragma unroll
        for (int mt = 0; mt < 2; mt++)
            #pragma unroll
            for (int rh = 0; rh < 2; rh++) {
                int row = m0 + wm * 32 + mt * 16 + (lane >> 2) + rh * 8;
                atomicAdd(&g_rowsum[row], ps[mt * 2 + rh]);
            }
    }
}

__global__ void zero_kernel() {
    for (int i = threadIdx.x; i < SEQ; i += blockDim.x) g_rowsum[i] = 0.f;
}

__global__ void loss_kernel(float* out_f) {
    float s = 0.f;
    for (int t = threadIdx.x; t < SEQ; t += blockDim.x)
        s += CAPV + logf(g_rowsum[t]) - g_tl[t];
    s = blockReduceSum(s);
    if (threadIdx.x == 0 && out_f) out_f[0] = s / (float)SEQ;
}

// ---------------- launch ------------------------------------------------------
extern "C" void kernel_launch(void* const* d_in, const int* in_sizes, int n_in,
                              void* d_out, int out_size) {
    const int*   idx     = (const int*)d_in[0];
    const int*   targets = (const int*)d_in[1];
    const float* emb     = (const float*)d_in[2];
    const float* ln1_w   = (const float*)d_in[3];
    const float* qkv_w   = (const float*)d_in[4];
    const float* q_norm  = (const float*)d_in[5];
    const float* k_norm  = (const float*)d_in[6];
    const float* proj_w  = (const float*)d_in[7];
    const float* ln2_w   = (const float*)d_in[8];
    const float* fc1_w   = (const float*)d_in[9];
    const float* fc2_w   = (const float*)d_in[10];
    const float* lnf_w   = (const float*)d_in[11];
    const float* lm_w    = (const float*)d_in[12];

    float *p_x, *p_big;
    cudaGetSymbolAddress((void**)&p_x, g_x);
    cudaGetSymbolAddress((void**)&p_big, g_big);
    __nv_bfloat16 *pqkv, *pproj, *pfc1, *pfc2, *plm, *pan3, *pah3;
    cudaGetSymbolAddress((void**)&pqkv, w3_qkv);
    cudaGetSymbolAddress((void**)&pproj, w3_proj);
    cudaGetSymbolAddress((void**)&pfc1, w3_fc1);
    cudaGetSymbolAddress((void**)&pfc2, w3_fc2);
    cudaGetSymbolAddress((void**)&plm, w3_lm);
    cudaGetSymbolAddress((void**)&pan3, an3);
    cudaGetSymbolAddress((void**)&pah3, ah3);

    cudaFuncSetAttribute(gemm_kernel,
                         cudaFuncAttributeMaxDynamicSharedMemorySize, SMEM_BYTES);
    cudaFuncSetAttribute(lmhead_kernel,
                         cudaFuncAttributeMaxDynamicSharedMemorySize, SMEM_BYTES);

    const long long NTV = (long long)SEQ * VOCAB;
    int store_logits = ((long long)out_size >= NTV) ? 1 : 0;

    // Launch order keeps the qkv GEMM of layer 0 at launch index 5 so the
    // ncu capture (-s 5 -c 1) lands on the GEMM.
    split_all_kernel<<<8192, 256>>>((const float4*)qkv_w, (const float4*)proj_w,
                                    (const float4*)fc1_w, (const float4*)fc2_w,
                                    (const float4*)lm_w,
                                    pqkv, pproj, pfc1, pfc2, plm);   // 0
    embed_kernel<<<SEQ, 256>>>(idx, emb);                            // 1
    zero_kernel<<<1, 256>>>();                                       // 2
    zero_kernel<<<1, 256>>>();                                       // 3 (pad, idempotent)

    for (int l = 0; l < LNUM; l++) {
        const float* l1 = ln1_w + (size_t)l * DMODEL;
        const float* qn = q_norm + (size_t)l * HDIM;
        const float* kn = k_norm + (size_t)l * HDIM;
        const float* l2 = ln2_w + (size_t)l * DMODEL;
        __nv_bfloat16* qkw = pqkv + (size_t)l * 2304 * K3D;
        __nv_bfloat16* pw  = pproj + (size_t)l * 768 * K3D;
        __nv_bfloat16* f1  = pfc1 + (size_t)l * 3072 * K3D;
        __nv_bfloat16* f2  = pfc2 + (size_t)l * 768 * K3F;

        rmsnorm_kernel<<<SEQ, 256>>>(p_x, l1);                       // 4 (l=0)
        gemm_kernel<<<dim3(SEQ / BM, 2304 / BN), 256, SMEM_BYTES>>>( // 5 (l=0)
            pan3, qkw, p_big, nullptr, nullptr, 2304, K3D, 0);
        {
            dim3 g(SEQ, NHEAD);
            rope_kernel<<<g, HDIM>>>(p_big, qn, kn);
        }
        {
            dim3 g(SEQ / 8, NHEAD);
            attn_kernel<<<g, 256>>>();
        }
        gemm_kernel<<<dim3(SEQ / BM, DMODEL / BN), 256, SMEM_BYTES>>>(
            pan3, pw, p_x, p_x, nullptr, DMODEL, K3D, 1);
        rmsnorm_kernel<<<SEQ, 256>>>(p_x, l2);
        gemm_kernel<<<dim3(SEQ / BM, FFDIM / BN), 256, SMEM_BYTES>>>(
            pan3, f1, nullptr, nullptr, pah3, FFDIM, K3D, 2);
        gemm_kernel<<<dim3(SEQ / BM, DMODEL / BN), 256, SMEM_BYTES>>>(
            pah3, f2, p_x, p_x, nullptr, DMODEL, K3F, 1);
    }

    rmsnorm_kernel<<<SEQ, 256>>>(p_x, lnf_w);
    lmhead_kernel<<<dim3(SEQ / BM, VOCAB / BN), 256, SMEM_BYTES>>>(
        pan3, plm, (float*)d_out, targets, store_logits);
    if (store_logits) {
        float* lossp =
            ((long long)out_size > NTV) ? ((float*)d_out + NTV) : nullptr;
        loss_kernel<<<1, 256>>>(lossp);
    } else {
        loss_kernel<<<1, 256>>>((float*)d_out);
    }
}

// round 8
// speedup vs baseline: 1.4535x; 1.4535x over previous
#include <cuda_runtime.h>
#include <cuda_bf16.h>
#include <math.h>
#include <stdint.h>

// Model dims
#define LNUM 12
#define DMODEL 768
#define NHEAD 6
#define HDIM 128
#define FFDIM 3072
#define VOCAB 65536
#define SEQ 2048
#define EPSV 1e-5f
#define CAPV 30.0f

#define K3D (3 * DMODEL)    // 2304
#define K3F (3 * FFDIM)     // 9216

// GEMM tiling (r4 best variant): 128x128 tile, BK=64, 3-stage cp.async
#define LDS 72
#define SMEM_BYTES (3 * 128 * LDS * 2 * 2)

// ---------------- scratch (static device arrays; no allocation) -------------
__device__ float g_x[SEQ * DMODEL];
__device__ float g_big[SEQ * K3D];
__device__ float g_q[SEQ * DMODEL];
__device__ float g_k[SEQ * DMODEL];
__device__ float g_v[SEQ * DMODEL];
__device__ float g_rowsum[SEQ];
__device__ float g_tl[SEQ];

// K-interleaved bf16x3 weight planes: row n, cols [0,K)=hi,[K,2K)=lo,[2K,3K)=hi
__device__ __align__(16) __nv_bfloat16 w3_qkv[12LL * 2304 * K3D];
__device__ __align__(16) __nv_bfloat16 w3_proj[12LL * 768 * K3D];
__device__ __align__(16) __nv_bfloat16 w3_fc1[12LL * 3072 * K3D];
__device__ __align__(16) __nv_bfloat16 w3_fc2[12LL * 768 * K3F];
__device__ __align__(16) __nv_bfloat16 w3_lm[65536LL * K3D];

// K-interleaved activation planes: row t, cols [0,K)=hi,[K,2K)=hi,[2K,3K)=lo
__device__ __align__(16) __nv_bfloat16 an3[SEQ * K3D];
__device__ __align__(16) __nv_bfloat16 ah3[SEQ * K3F];

// ---------------- helpers ----------------------------------------------------
__device__ __forceinline__ void split2(float v, __nv_bfloat16& h, __nv_bfloat16& l) {
    h = __float2bfloat16(v);
    l = __float2bfloat16(v - __bfloat162float(h));
}

__device__ __forceinline__ float blockReduceSum(float v) {
    __shared__ float sh[32];
    __syncthreads();
    int lane = threadIdx.x & 31, wid = threadIdx.x >> 5;
    #pragma unroll
    for (int o = 16; o; o >>= 1) v += __shfl_xor_sync(0xffffffffu, v, o);
    if (lane == 0) sh[wid] = v;
    __syncthreads();
    int nw = blockDim.x >> 5;
    v = (threadIdx.x < nw) ? sh[threadIdx.x] : 0.f;
    if (wid == 0) {
        #pragma unroll
        for (int o = 16; o; o >>= 1) v += __shfl_xor_sync(0xffffffffu, v, o);
        if (lane == 0) sh[0] = v;
    }
    __syncthreads();
    return sh[0];
}

__device__ __forceinline__ void ldsm4(uint32_t (&r)[4], uint32_t addr) {
    asm volatile("ldmatrix.sync.aligned.m8n8.x4.shared.b16 {%0,%1,%2,%3},[%4];"
                 : "=r"(r[0]), "=r"(r[1]), "=r"(r[2]), "=r"(r[3]) : "r"(addr));
}

__device__ __forceinline__ void mma_bf16(float (&d)[4], const uint32_t (&a)[4],
                                         uint32_t b0, uint32_t b1) {
    asm volatile(
        "mma.sync.aligned.m16n8k16.row.col.f32.bf16.bf16.f32 "
        "{%0,%1,%2,%3},{%4,%5,%6,%7},{%8,%9},{%0,%1,%2,%3};"
        : "+f"(d[0]), "+f"(d[1]), "+f"(d[2]), "+f"(d[3])
        : "r"(a[0]), "r"(a[1]), "r"(a[2]), "r"(a[3]), "r"(b0), "r"(b1));
}

__device__ __forceinline__ void cp16(uint32_t dst, const void* src) {
    asm volatile("cp.async.cg.shared.global [%0], [%1], 16;" :: "r"(dst), "l"(src));
}
#define CP_COMMIT() asm volatile("cp.async.commit_group;")
#define CP_WAIT1() asm volatile("cp.async.wait_group 1;")

// load one 128x64 bf16 tile of A and B into a stage (8 cp.async per thread)
__device__ __forceinline__ void load_stage(uint32_t sA, uint32_t sB,
                                           const __nv_bfloat16* gA,
                                           const __nv_bfloat16* gB,
                                           int Kp, int tid) {
    int tRow = tid >> 3, tc = (tid & 7) * 8;
    #pragma unroll
    for (int p = 0; p < 4; p++) {
        int row = tRow + 32 * p;
        cp16(sA + (uint32_t)(row * LDS + tc) * 2, gA + (size_t)row * Kp + tc);
        cp16(sB + (uint32_t)(row * LDS + tc) * 2, gB + (size_t)row * Kp + tc);
    }
}

// ---------------- fused weight split: 5 tensors, ONE launch -------------------
__device__ __forceinline__ void split_seg(const float4* s, __nv_bfloat16* d,
                                          long long n4, int K,
                                          long long gid, long long gstride) {
    for (long long i = gid; i < n4; i += gstride) {
        float4 v = s[i];
        long long o = i * 4;
        long long n = o / K;
        int k = (int)(o - n * K);
        __nv_bfloat16* r = d + n * 3LL * K + k;
        float vv[4] = {v.x, v.y, v.z, v.w};
        #pragma unroll
        for (int j = 0; j < 4; j++) {
            __nv_bfloat16 h, l;
            split2(vv[j], h, l);
            r[j] = h; r[K + j] = l; r[2 * K + j] = h;
        }
    }
}

__global__ void split_all_kernel(const float4* qkv, const float4* proj,
                                 const float4* fc1, const float4* fc2,
                                 const float4* lm,
                                 __nv_bfloat16* dqkv, __nv_bfloat16* dproj,
                                 __nv_bfloat16* dfc1, __nv_bfloat16* dfc2,
                                 __nv_bfloat16* dlm) {
    long long gid = blockIdx.x * (long long)blockDim.x + threadIdx.x;
    long long gs = gridDim.x * (long long)blockDim.x;
    split_seg(qkv, dqkv, 12LL * 2304 * 768 / 4, DMODEL, gid, gs);
    split_seg(proj, dproj, 12LL * 768 * 768 / 4, DMODEL, gid, gs);
    split_seg(fc1, dfc1, 12LL * 3072 * 768 / 4, DMODEL, gid, gs);
    split_seg(fc2, dfc2, 12LL * 768 * 3072 / 4, FFDIM, gid, gs);
    split_seg(lm, dlm, 65536LL * 768 / 4, DMODEL, gid, gs);
}

// ---------------- elementwise kernels ----------------------------------------
__global__ void embed_kernel(const int* __restrict__ idx,
                             const float* __restrict__ emb) {
    int t = blockIdx.x;
    int row = idx[t];
    const float* src = emb + (size_t)row * DMODEL;
    for (int i = threadIdx.x; i < DMODEL; i += blockDim.x)
        g_x[t * DMODEL + i] = src[i];
}

__global__ void rmsnorm_kernel(const float* __restrict__ x,
                               const float* __restrict__ w) {
    int t = blockIdx.x;
    const float* xr = x + (size_t)t * DMODEL;
    float s = 0.f;
    for (int i = threadIdx.x; i < DMODEL; i += blockDim.x) {
        float v = xr[i];
        s += v * v;
    }
    s = blockReduceSum(s);
    float r = rsqrtf(s / (float)DMODEL + EPSV);
    for (int i = threadIdx.x; i < DMODEL; i += blockDim.x) {
        float v = xr[i] * r * w[i];
        __nv_bfloat16 h, l;
        split2(v, h, l);
        size_t o = (size_t)t * K3D + i;
        an3[o] = h; an3[o + DMODEL] = h; an3[o + 2 * DMODEL] = l;
    }
}

__global__ void rope_kernel(const float* __restrict__ qkv,
                            const float* __restrict__ qw,
                            const float* __restrict__ kw) {
    int t = blockIdx.x, h = blockIdx.y, d = threadIdx.x;
    const float* base = qkv + (size_t)t * K3D;
    float qd = base[h * HDIM + d];
    float kd = base[DMODEL + h * HDIM + d];
    float vd = base[2 * DMODEL + h * HDIM + d];
    float qs = blockReduceSum(qd * qd);
    float ks = blockReduceSum(kd * kd);
    float qn = qd * rsqrtf(qs / (float)HDIM + EPSV) * qw[d];
    float kn = kd * rsqrtf(ks / (float)HDIM + EPSV) * kw[d];
    __shared__ float sq[HDIM], sk[HDIM];
    sq[d] = qn; sk[d] = kn;
    __syncthreads();
    float expo = -(float)((d & 63) * 2) / (float)HDIM;
    float invf = expf(expo * logf(10000.f));
    float ang = (float)t * invf;
    float c = cosf(ang), s = sinf(ang);
    float qr = (d < 64) ? -sq[d + 64] : sq[d - 64];
    float kr = (d < 64) ? -sk[d + 64] : sk[d - 64];
    size_t oidx = (size_t)t * DMODEL + h * HDIM + d;
    g_q[oidx] = qn * c + qr * s;
    g_k[oidx] = kn * c + kr * s;
    g_v[oidx] = vd;
}

// ---------------- attention: tile-wise online softmax (lane = key) -----------
// Block: 8 warps, warp w handles query qbase+w. 32-key tiles.
// Scores for 32 keys computed in parallel (lane j = key j), ONE softmax
// update per tile. K stored float4-transposed, V float4 row-major.
__global__ void __launch_bounds__(256) attn_kernel() {
    const int h = blockIdx.y;
    const int qbase = blockIdx.x * 8;
    const int tid = threadIdx.x;
    const int warp = tid >> 5, lane = tid & 31;
    const int qi = qbase + warp;
    __shared__ float4 Ktf[32][33];   // Ktf[d4][j] = K[j][4*d4..4*d4+3]
    __shared__ float4 Vtf[32][33];   // Vtf[j][d4] = V[j][4*d4..4*d4+3]
    __shared__ float4 sq4[8][32];    // q per warp

    {
        int r = tid >> 5, c4 = tid & 31;
        sq4[r][c4] = ((const float4*)(g_q + (size_t)(qbase + r) * DMODEL +
                                      h * HDIM))[c4];
    }

    float m = -1e30f, l = 0.f;
    float4 acc = make_float4(0.f, 0.f, 0.f, 0.f);
    const int ntiles = (qbase + 8 + 31) >> 5;

    for (int tb = 0; tb < ntiles; tb++) {
        int kb = tb << 5;
        __syncthreads();
        #pragma unroll
        for (int it = 0; it < 4; it++) {
            int i = tid + it * 256;
            int r = i >> 5, c4 = i & 31;
            Ktf[c4][r] = ((const float4*)(g_k + (size_t)(kb + r) * DMODEL +
                                          h * HDIM))[c4];
            Vtf[r][c4] = ((const float4*)(g_v + (size_t)(kb + r) * DMODEL +
                                          h * HDIM))[c4];
        }
        __syncthreads();

        int jmax = qi - kb + 1;          // number of valid keys in this tile
        if (jmax > 0) {
            // scores: lane = key
            float s0 = 0.f, s1 = 0.f, s2 = 0.f, s3 = 0.f;
            #pragma unroll
            for (int d4 = 0; d4 < 32; d4 += 4) {
                float4 q0 = sq4[warp][d4],     k0 = Ktf[d4][lane];
                float4 q1 = sq4[warp][d4 + 1], k1 = Ktf[d4 + 1][lane];
                float4 q2 = sq4[warp][d4 + 2], k2 = Ktf[d4 + 2][lane];
                float4 q3 = sq4[warp][d4 + 3], k3 = Ktf[d4 + 3][lane];
                s0 += q0.x * k0.x + q0.y * k0.y + q0.z * k0.z + q0.w * k0.w;
                s1 += q1.x * k1.x + q1.y * k1.y + q1.z * k1.z + q1.w * k1.w;
                s2 += q2.x * k2.x + q2.y * k2.y + q2.z * k2.z + q2.w * k2.w;
                s3 += q3.x * k3.x + q3.y * k3.y + q3.z * k3.z + q3.w * k3.w;
            }
            float sv = (s0 + s1 + s2 + s3) * 0.08838834764831845f;
            if (lane >= jmax) sv = -1e30f;
            // tile max
            float mt = sv;
            #pragma unroll
            for (int o = 16; o; o >>= 1)
                mt = fmaxf(mt, __shfl_xor_sync(0xffffffffu, mt, o));
            float mn = fmaxf(m, mt);
            float corr = __expf(m - mn);
            float p = __expf(sv - mn);          // masked lanes -> 0
            float psum = p;
            #pragma unroll
            for (int o = 16; o; o >>= 1)
                psum += __shfl_xor_sync(0xffffffffu, psum, o);
            l = l * corr + psum;
            m = mn;
            acc.x *= corr; acc.y *= corr; acc.z *= corr; acc.w *= corr;
            #pragma unroll
            for (int j = 0; j < 32; j++) {
                float pj = __shfl_sync(0xffffffffu, p, j);
                float4 vv = Vtf[j][lane];
                acc.x += pj * vv.x; acc.y += pj * vv.y;
                acc.z += pj * vv.z; acc.w += pj * vv.w;
            }
        }
    }
    float inv = 1.f / l;
    // lane owns dims [lane*4, lane*4+4)
    float ov[4] = {acc.x * inv, acc.y * inv, acc.z * inv, acc.w * inv};
    #pragma unroll
    for (int q = 0; q < 4; q++) {
        int i = h * HDIM + lane * 4 + q;
        __nv_bfloat16 hh, ll;
        split2(ov[q], hh, ll);
        size_t o = (size_t)qi * K3D + i;
        an3[o] = hh; an3[o + DMODEL] = hh; an3[o + 2 * DMODEL] = ll;
    }
}

// ---------------- pipelined bf16 GEMM (r4 verbatim): C = A * B^T --------------
__global__ void __launch_bounds__(256, 1)
gemm_kernel(const __nv_bfloat16* __restrict__ A, const __nv_bfloat16* __restrict__ B,
            float* __restrict__ C, const float* __restrict__ res,
            __nv_bfloat16* __restrict__ O3,
            int M, int N, int Kp, int epi) {
    extern __shared__ __nv_bfloat16 smem[];
    __nv_bfloat16* sA = smem;
    __nv_bfloat16* sB = smem + 3 * 128 * LDS;
    const int tid = threadIdx.x, lane = tid & 31, wid = tid >> 5;
    const int wm = wid >> 2, wn = wid & 3;
    const int m0 = blockIdx.x * 128, n0 = blockIdx.y * 128;
    const uint32_t sAu = (uint32_t)__cvta_generic_to_shared(sA);
    const uint32_t sBu = (uint32_t)__cvta_generic_to_shared(sB);
    const uint32_t stageB = 128 * LDS * 2;
    const __nv_bfloat16* gA = A + (size_t)m0 * Kp;
    const __nv_bfloat16* gB = B + (size_t)n0 * Kp;

    float acc[4][4][4];
    #pragma unroll
    for (int a = 0; a < 4; a++)
        #pragma unroll
        for (int b = 0; b < 4; b++)
            #pragma unroll
            for (int c = 0; c < 4; c++) acc[a][b][c] = 0.f;

    const int nk = Kp / 64;
    load_stage(sAu, sBu, gA, gB, Kp, tid);
    CP_COMMIT();
    load_stage(sAu + stageB, sBu + stageB, gA + 64, gB + 64, Kp, tid);
    CP_COMMIT();

    for (int k = 0; k < nk; k++) {
        CP_WAIT1();
        __syncthreads();
        int st = k % 3;
        uint32_t aB = sAu + st * stageB;
        uint32_t bB = sBu + st * stageB;
        #pragma unroll
        for (int kh = 0; kh < 4; kh++) {
            uint32_t a[4][4], b[2][4];
            const int acol = kh * 16 + ((lane >> 4) << 3);
            #pragma unroll
            for (int mt = 0; mt < 4; mt++) {
                int arow = wm * 64 + mt * 16 + (lane & 15);
                ldsm4(a[mt], aB + (uint32_t)(arow * LDS + acol) * 2);
            }
            const int brow = wn * 32 + ((lane >> 4) << 3) + (lane & 7);
            const int bcol = kh * 16 + (((lane >> 3) & 1) << 3);
            #pragma unroll
            for (int p = 0; p < 2; p++)
                ldsm4(b[p], bB + (uint32_t)((brow + p * 16) * LDS + bcol) * 2);
            #pragma unroll
            for (int mt = 0; mt < 4; mt++)
                #pragma unroll
                for (int nt = 0; nt < 4; nt++)
                    mma_bf16(acc[mt][nt], a[mt], b[nt >> 1][(nt & 1) * 2],
                             b[nt >> 1][(nt & 1) * 2 + 1]);
        }
        if (k + 2 < nk) {
            int s2 = (k + 2) % 3;
            load_stage(sAu + s2 * stageB, sBu + s2 * stageB,
                       gA + (size_t)(k + 2) * 64, gB + (size_t)(k + 2) * 64,
                       Kp, tid);
        }
        CP_COMMIT();
    }
    #pragma unroll
    for (int mt = 0; mt < 4; mt++)
        #pragma unroll
        for (int nt = 0; nt < 4; nt++)
            #pragma unroll
            for (int r = 0; r < 4; r++) {
                int row = m0 + wm * 64 + mt * 16 + (lane >> 2) + (r >> 1) * 8;
                int col = n0 + wn * 32 + nt * 8 + (lane & 3) * 2 + (r & 1);
                float vv = acc[mt][nt][r];
                if (epi == 0) {
                    C[(size_t)row * N + col] = vv;
                } else if (epi == 1) {
                    size_t o = (size_t)row * N + col;
                    C[o] = vv + res[o];
                } else {
                    vv = fmaxf(vv, 0.f); vv = vv * vv;
                    __nv_bfloat16 h, l;
                    split2(vv, h, l);
                    size_t o = (size_t)row * 3 * N + col;
                    O3[o] = h; O3[o + N] = h; O3[o + 2 * N] = l;
                }
            }
}

// ---------------- lm_head (r4 verbatim): GEMM + softcap/store/lse ------------
__global__ void __launch_bounds__(256, 1)
lmhead_kernel(const __nv_bfloat16* __restrict__ A, const __nv_bfloat16* __restrict__ B,
              float* __restrict__ out, const int* __restrict__ targets, int store) {
    const int N = VOCAB, Kp = K3D;
    extern __shared__ __nv_bfloat16 smem[];
    __nv_bfloat16* sA = smem;
    __nv_bfloat16* sB = smem + 3 * 128 * LDS;
    const int tid = threadIdx.x, lane = tid & 31, wid = tid >> 5;
    const int wm = wid >> 2, wn = wid & 3;
    const int m0 = blockIdx.x * 128, n0 = blockIdx.y * 128;
    const uint32_t sAu = (uint32_t)__cvta_generic_to_shared(sA);
    const uint32_t sBu = (uint32_t)__cvta_generic_to_shared(sB);
    const uint32_t stageB = 128 * LDS * 2;
    const __nv_bfloat16* gA = A + (size_t)m0 * Kp;
    const __nv_bfloat16* gB = B + (size_t)n0 * Kp;

    float acc[4][4][4];
    #pragma unroll
    for (int a = 0; a < 4; a++)
        #pragma unroll
        for (int b = 0; b < 4; b++)
            #pragma unroll
            for (int c = 0; c < 4; c++) acc[a][b][c] = 0.f;

    const int nk = Kp / 64;
    load_stage(sAu, sBu, gA, gB, Kp, tid);
    CP_COMMIT();
    load_stage(sAu + stageB, sBu + stageB, gA + 64, gB + 64, Kp, tid);
    CP_COMMIT();

    for (int k = 0; k < nk; k++) {
        CP_WAIT1();
        __syncthreads();
        int st = k % 3;
        uint32_t aB = sAu + st * stageB;
        uint32_t bB = sBu + st * stageB;
        #pragma unroll
        for (int kh = 0; kh < 4; kh++) {
            uint32_t a[4][4], b[2][4];
            const int acol = kh * 16 + ((lane >> 4) << 3);
            #pragma unroll
            for (int mt = 0; mt < 4; mt++) {
                int arow = wm * 64 + mt * 16 + (lane & 15);
                ldsm4(a[mt], aB + (uint32_t)(arow * LDS + acol) * 2);
            }
            const int brow = wn * 32 + ((lane >> 4) << 3) + (lane & 7);
            const int bcol = kh * 16 + (((lane >> 3) & 1) << 3);
            #pragma unroll
            for (int p = 0; p < 2; p++)
                ldsm4(b[p], bB + (uint32_t)((brow + p * 16) * LDS + bcol) * 2);
            #pragma unroll
            for (int mt = 0; mt < 4; mt++)
                #pragma unroll
                for (int nt = 0; nt < 4; nt++)
                    mma_bf16(acc[mt][nt], a[mt], b[nt >> 1][(nt & 1) * 2],
                             b[nt >> 1][(nt & 1) * 2 + 1]);
        }
        if (k + 2 < nk) {
            int s2 = (k + 2) % 3;
            load_stage(sAu + s2 * stageB, sBu + s2 * stageB,
                       gA + (size_t)(k + 2) * 64, gB + (size_t)(k + 2) * 64,
                       Kp, tid);
        }
        CP_COMMIT();
    }
    float ps[8];
    #pragma unroll
    for (int i = 0; i < 8; i++) ps[i] = 0.f;
    #pragma unroll
    for (int mt = 0; mt < 4; mt++)
        #pragma unroll
        for (int nt = 0; nt < 4; nt++)
            #pragma unroll
            for (int r = 0; r < 4; r++) {
                int row = m0 + wm * 64 + mt * 16 + (lane >> 2) + (r >> 1) * 8;
                int col = n0 + wn * 32 + nt * 8 + (lane & 3) * 2 + (r & 1);
                float vv = CAPV * tanhf(acc[mt][nt][r] * (1.f / CAPV));
                if (store)
                    out[(size_t)row * N + col] =
                        __bfloat162float(__float2bfloat16(vv));
                ps[mt * 2 + (r >> 1)] += __expf(vv - CAPV);
                if (col == targets[row]) g_tl[row] = vv;
            }
    #pragma unroll
    for (int i = 0; i < 8; i++) {
        ps[i] += __shfl_xor_sync(0xffffffffu, ps[i], 1);
        ps[i] += __shfl_xor_sync(0xffffffffu, ps[i], 2);
    }
    __syncthreads();
    float* red = (float*)smem;  // [128][4]
    if ((lane & 3) == 0) {
        #pragma unroll
        for (int mt = 0; mt < 4; mt++)
            #pragma unroll
            for (int hh = 0; hh < 2; hh++) {
                int rl = wm * 64 + mt * 16 + (lane >> 2) + hh * 8;
                red[rl * 4 + wn] = ps[mt * 2 + hh];
            }
    }
    __syncthreads();
    if (tid < 128) {
        float s = red[tid * 4] + red[tid * 4 + 1] + red[tid * 4 + 2] + red[tid * 4 + 3];
        atomicAdd(&g_rowsum[m0 + tid], s);
    }
}

__global__ void zero_kernel() {
    for (int i = threadIdx.x; i < SEQ; i += blockDim.x) g_rowsum[i] = 0.f;
}

__global__ void loss_kernel(float* out_f) {
    float s = 0.f;
    for (int t = threadIdx.x; t < SEQ; t += blockDim.x)
        s += CAPV + logf(g_rowsum[t]) - g_tl[t];
    s = blockReduceSum(s);
    if (threadIdx.x == 0 && out_f) out_f[0] = s / (float)SEQ;
}

// ---------------- launch ------------------------------------------------------
extern "C" void kernel_launch(void* const* d_in, const int* in_sizes, int n_in,
                              void* d_out, int out_size) {
    const int*   idx     = (const int*)d_in[0];
    const int*   targets = (const int*)d_in[1];
    const float* emb     = (const float*)d_in[2];
    const float* ln1_w   = (const float*)d_in[3];
    const float* qkv_w   = (const float*)d_in[4];
    const float* q_norm  = (const float*)d_in[5];
    const float* k_norm  = (const float*)d_in[6];
    const float* proj_w  = (const float*)d_in[7];
    const float* ln2_w   = (const float*)d_in[8];
    const float* fc1_w   = (const float*)d_in[9];
    const float* fc2_w   = (const float*)d_in[10];
    const float* lnf_w   = (const float*)d_in[11];
    const float* lm_w    = (const float*)d_in[12];

    float *p_x, *p_big;
    cudaGetSymbolAddress((void**)&p_x, g_x);
    cudaGetSymbolAddress((void**)&p_big, g_big);
    __nv_bfloat16 *pqkv, *pproj, *pfc1, *pfc2, *plm, *pan3, *pah3;
    cudaGetSymbolAddress((void**)&pqkv, w3_qkv);
    cudaGetSymbolAddress((void**)&pproj, w3_proj);
    cudaGetSymbolAddress((void**)&pfc1, w3_fc1);
    cudaGetSymbolAddress((void**)&pfc2, w3_fc2);
    cudaGetSymbolAddress((void**)&plm, w3_lm);
    cudaGetSymbolAddress((void**)&pan3, an3);
    cudaGetSymbolAddress((void**)&pah3, ah3);

    cudaFuncSetAttribute(gemm_kernel,
                         cudaFuncAttributeMaxDynamicSharedMemorySize, SMEM_BYTES);
    cudaFuncSetAttribute(lmhead_kernel,
                         cudaFuncAttributeMaxDynamicSharedMemorySize, SMEM_BYTES);

    const long long NTV = (long long)SEQ * VOCAB;
    int store_logits = ((long long)out_size >= NTV) ? 1 : 0;

    split_all_kernel<<<8192, 256>>>((const float4*)qkv_w, (const float4*)proj_w,
                                    (const float4*)fc1_w, (const float4*)fc2_w,
                                    (const float4*)lm_w,
                                    pqkv, pproj, pfc1, pfc2, plm);
    embed_kernel<<<SEQ, 256>>>(idx, emb);
    zero_kernel<<<1, 256>>>();

    for (int l = 0; l < LNUM; l++) {
        const float* l1 = ln1_w + (size_t)l * DMODEL;
        const float* qn = q_norm + (size_t)l * HDIM;
        const float* kn = k_norm + (size_t)l * HDIM;
        const float* l2 = ln2_w + (size_t)l * DMODEL;
        __nv_bfloat16* qkw = pqkv + (size_t)l * 2304 * K3D;
        __nv_bfloat16* pw  = pproj + (size_t)l * 768 * K3D;
        __nv_bfloat16* f1  = pfc1 + (size_t)l * 3072 * K3D;
        __nv_bfloat16* f2  = pfc2 + (size_t)l * 768 * K3F;

        rmsnorm_kernel<<<SEQ, 256>>>(p_x, l1);
        gemm_kernel<<<dim3(SEQ / 128, 2304 / 128), 256, SMEM_BYTES>>>(
            pan3, qkw, p_big, nullptr, nullptr, SEQ, 2304, K3D, 0);
        {
            dim3 g(SEQ, NHEAD);
            rope_kernel<<<g, HDIM>>>(p_big, qn, kn);
        }
        {
            dim3 g(SEQ / 8, NHEAD);
            attn_kernel<<<g, 256>>>();
        }
        gemm_kernel<<<dim3(SEQ / 128, DMODEL / 128), 256, SMEM_BYTES>>>(
            pan3, pw, p_x, p_x, nullptr, SEQ, DMODEL, K3D, 1);
        rmsnorm_kernel<<<SEQ, 256>>>(p_x, l2);
        gemm_kernel<<<dim3(SEQ / 128, FFDIM / 128), 256, SMEM_BYTES>>>(
            pan3, f1, nullptr, nullptr, pah3, SEQ, FFDIM, K3D, 2);
        gemm_kernel<<<dim3(SEQ / 128, DMODEL / 128), 256, SMEM_BYTES>>>(
            pah3, f2, p_x, p_x, nullptr, SEQ, DMODEL, K3F, 1);
    }

    rmsnorm_kernel<<<SEQ, 256>>>(p_x, lnf_w);
    lmhead_kernel<<<dim3(SEQ / 128, VOCAB / 128), 256, SMEM_BYTES>>>(
        pan3, plm, (float*)d_out, targets, store_logits);
    if (store_logits) {
        float* lossp =
            ((long long)out_size > NTV) ? ((float*)d_out + NTV) : nullptr;
        loss_kernel<<<1, 256>>>(lossp);
    } else {
        loss_kernel<<<1, 256>>>((float*)d_out);
    }
}